// round 5
// baseline (speedup 1.0000x reference)
#include <cuda_runtime.h>
#include <math.h>

#define NTHREADS 256
#define MROWS    64

typedef unsigned long long u64;

__device__ __forceinline__ u64 ffma2(u64 a, u64 b, u64 c) {
    u64 d;
    asm("fma.rn.f32x2 %0, %1, %2, %3;" : "=l"(d) : "l"(a), "l"(b), "l"(c));
    return d;
}
__device__ __forceinline__ u64 pack2(float x) {
    unsigned xi = __float_as_uint(x);
    u64 r;
    asm("mov.b64 %0, {%1, %2};" : "=l"(r) : "r"(xi), "r"(xi));
    return r;
}
__device__ __forceinline__ float2 unpack2(u64 v) {
    unsigned lo, hi;
    asm("mov.b64 {%0, %1}, %2;" : "=r"(lo), "=r"(hi) : "l"(v));
    return make_float2(__uint_as_float(lo), __uint_as_float(hi));
}

// ---- shared memory layout (float offsets) ----
#define XB_OFF   0          // phase1 x chunk [64][36]=2304 ; FM x chunk [64][68]=4352
#define XB1LD    36
#define XBFLD    68
#define WB_OFF   4352       // phase1 w chunk [32][128]=4096 ; FM a[64][16]+b[64][16] ; scratch
#define H1_OFF   12544      // [64][132] = 8448 -> ends 20992
#define H1LD     132
#define LIN_OFF  20992      // 64
#define FM2_OFF  21056      // 64
#define SB_OFF   21120      // 16
#define LINW_OFF 21136      // 512
#define WO_OFF   21648      // 32
#define SMEM_FLOATS 21680   // 86720 bytes -> 2 CTAs/SM
// overlays after FM is done with XB/WB:
#define W2_OFF   0          // 8192
#define H2_OFF   8192       // [64][68] = 4352 -> ends exactly at 12544 (H1 start)
#define H2LD     68
#define W3_OFF   0          // 2048 (loaded after phase2 finishes reading W2)
#define H3_OFF   2048       // [64][36] = 2304
#define H3LD     36

extern __shared__ float sm[];

__global__ __launch_bounds__(NTHREADS, 2)
void deepfm_fused_kernel(
    const float* __restrict__ x,     const float* __restrict__ fm_w,
    const float* __restrict__ fm_b,  const float* __restrict__ lin_w,
    const float* __restrict__ lin_b, const float* __restrict__ w1,
    const float* __restrict__ b1,    const float* __restrict__ w2,
    const float* __restrict__ b2,    const float* __restrict__ w3,
    const float* __restrict__ b3,    const float* __restrict__ wo,
    const float* __restrict__ bo,    const float* __restrict__ bias,
    float* __restrict__ out)
{
    const int tid = threadIdx.x;
    const int r0  = blockIdx.x * MROWS;
    const float4* gx = (const float4*)(x + (size_t)r0 * 512);

    // lane-mapped tiling: within a warp, 4 row-groups x 8 col-groups (cuts smem wavefronts)
    const int rg = (tid & 3) | (((tid >> 5) & 3) << 2);   // 0..15
    const int cg = ((tid >> 2) & 7) | ((tid >> 7) << 3);  // 0..15

    // stage lin_w (512) and wo (32) once
    if (tid < 128) {
        *(float4*)&sm[LINW_OFF + tid * 4] = ((const float4*)lin_w)[tid];
    } else if (tid < 136) {
        *(float4*)&sm[WO_OFF + (tid - 128) * 4] = ((const float4*)wo)[tid - 128];
    }

    // ================= Phase 1: h1 = relu(x @ W1 + b1), f32x2 packed =================
    {
        const int rbase = rg * 4;
        const int cbase = cg * 8;
        u64 acc2[4][4];
        #pragma unroll
        for (int i = 0; i < 4; i++)
            #pragma unroll
            for (int j = 0; j < 4; j++) acc2[i][j] = 0ull;

        for (int k0 = 0; k0 < 512; k0 += 32) {
            __syncthreads();
            // stage x[:, k0:k0+32] -> XB [64][36]
            #pragma unroll
            for (int l = 0; l < 2; l++) {
                int idx = tid + l * NTHREADS;          // 512 float4s
                int row = idx >> 3, c4 = idx & 7;
                *(float4*)&sm[XB_OFF + row * XB1LD + c4 * 4] = gx[row * 128 + (k0 >> 2) + c4];
            }
            // stage w1[k0:k0+32, :] -> WB (contiguous 4096 floats)
            const float4* gw = (const float4*)(w1 + k0 * 128);
            #pragma unroll
            for (int l = 0; l < 4; l++) {
                int idx = tid + l * NTHREADS;
                *(float4*)&sm[WB_OFF + idx * 4] = gw[idx];
            }
            __syncthreads();

            #pragma unroll
            for (int kk = 0; kk < 32; kk += 4) {
                float xs[4][4];
                #pragma unroll
                for (int i = 0; i < 4; i++) {
                    float4 v = *(const float4*)&sm[XB_OFF + (rbase + i) * XB1LD + kk];
                    xs[i][0] = v.x; xs[i][1] = v.y; xs[i][2] = v.z; xs[i][3] = v.w;
                }
                #pragma unroll
                for (int q = 0; q < 4; q++) {
                    ulonglong2 wa = *(const ulonglong2*)&sm[WB_OFF + (kk + q) * 128 + cbase];
                    ulonglong2 wb = *(const ulonglong2*)&sm[WB_OFF + (kk + q) * 128 + cbase + 4];
                    #pragma unroll
                    for (int i = 0; i < 4; i++) {
                        u64 xq2 = pack2(xs[i][q]);
                        acc2[i][0] = ffma2(xq2, wa.x, acc2[i][0]);
                        acc2[i][1] = ffma2(xq2, wa.y, acc2[i][1]);
                        acc2[i][2] = ffma2(xq2, wb.x, acc2[i][2]);
                        acc2[i][3] = ffma2(xq2, wb.y, acc2[i][3]);
                    }
                }
            }
        }
        // epilogue: +b1, relu, -> h1
        float4 bb0 = __ldg((const float4*)&b1[cbase]);
        float4 bb1 = __ldg((const float4*)&b1[cbase + 4]);
        #pragma unroll
        for (int i = 0; i < 4; i++) {
            float2 p0 = unpack2(acc2[i][0]);
            float2 p1 = unpack2(acc2[i][1]);
            float2 p2 = unpack2(acc2[i][2]);
            float2 p3 = unpack2(acc2[i][3]);
            float4 o0, o1;
            o0.x = fmaxf(p0.x + bb0.x, 0.f);
            o0.y = fmaxf(p0.y + bb0.y, 0.f);
            o0.z = fmaxf(p1.x + bb0.z, 0.f);
            o0.w = fmaxf(p1.y + bb0.w, 0.f);
            o1.x = fmaxf(p2.x + bb1.x, 0.f);
            o1.y = fmaxf(p2.y + bb1.y, 0.f);
            o1.z = fmaxf(p3.x + bb1.z, 0.f);
            o1.w = fmaxf(p3.y + bb1.w, 0.f);
            *(float4*)&sm[H1_OFF + (rbase + i) * H1LD + cbase]     = o0;
            *(float4*)&sm[H1_OFF + (rbase + i) * H1LD + cbase + 4] = o1;
        }
    }
    __syncthreads();   // phase-1 done reading WB

    // ================= Sb precompute: Sb[d] = sum_k fm_b[k][d]  (row-independent) =====
    {
        int d = tid & 15, seg = tid >> 4;
        float p = 0.f;
        #pragma unroll 8
        for (int j = 0; j < 32; j++) p += __ldg(&fm_b[(seg * 32 + j) * 16 + d]);
        sm[WB_OFF + seg * 16 + d] = p;   // WB as scratch
    }
    __syncthreads();
    if (tid < 16) {
        float s = 0.f;
        #pragma unroll
        for (int seg = 0; seg < 16; seg++) s += sm[WB_OFF + seg * 16 + tid];
        sm[SB_OFF + tid] = s;
    }

    // ================= FM phase (f32x2), streams x + fm_w/fm_b chunks ================
    {
        const int row = tid >> 2;      // 64 rows
        const int dg  = tid & 3;       // 2 d-pairs per thread
        u64 ssum2[2] = {0ull, 0ull};
        u64 ssq2[2]  = {0ull, 0ull};
        float s_lin = 0.f;

        for (int k0 = 0; k0 < 512; k0 += 64) {
            __syncthreads();   // also covers Sb scratch reads on first iter
            #pragma unroll
            for (int l = 0; l < 4; l++) {
                int idx = tid + l * NTHREADS;       // 1024 float4s
                int r = idx >> 4, c4 = idx & 15;
                *(float4*)&sm[XB_OFF + r * XBFLD + c4 * 4] = gx[r * 128 + (k0 >> 2) + c4];
            }
            *(float4*)&sm[WB_OFF + tid * 4]        = ((const float4*)(fm_w + k0 * 16))[tid];
            *(float4*)&sm[WB_OFF + 1024 + tid * 4] = ((const float4*)(fm_b + k0 * 16))[tid];
            __syncthreads();

            #pragma unroll 4
            for (int kk = 0; kk < 64; kk++) {
                float xv = sm[XB_OFF + row * XBFLD + kk];
                u64 x2 = pack2(xv);
                ulonglong2 a = *(const ulonglong2*)&sm[WB_OFF + kk * 16 + dg * 4];
                ulonglong2 b = *(const ulonglong2*)&sm[WB_OFF + 1024 + kk * 16 + dg * 4];
                ssum2[0] = ffma2(x2, a.x, ssum2[0]);
                ssum2[1] = ffma2(x2, a.y, ssum2[1]);
                u64 t0 = ffma2(x2, a.x, b.x);
                u64 t1 = ffma2(x2, a.y, b.y);
                ssq2[0] = ffma2(t0, t0, ssq2[0]);
                ssq2[1] = ffma2(t1, t1, ssq2[1]);
                if (dg == 0) s_lin = fmaf(xv, sm[LINW_OFF + k0 + kk], s_lin);
            }
        }
        float2 s0 = unpack2(ssum2[0]), s1 = unpack2(ssum2[1]);
        float2 q0 = unpack2(ssq2[0]),  q1 = unpack2(ssq2[1]);
        const int db = dg * 4;
        float v = 0.f, se;
        se = s0.x + sm[SB_OFF + db + 0]; v += se * se - q0.x;
        se = s0.y + sm[SB_OFF + db + 1]; v += se * se - q0.y;
        se = s1.x + sm[SB_OFF + db + 2]; v += se * se - q1.x;
        se = s1.y + sm[SB_OFF + db + 3]; v += se * se - q1.y;
        v += __shfl_xor_sync(0xffffffffu, v, 1);
        v += __shfl_xor_sync(0xffffffffu, v, 2);
        if (dg == 0) {
            sm[FM2_OFF + row] = 0.5f * v;
            sm[LIN_OFF + row] = s_lin;
        }
    }
    __syncthreads();   // FM done with XB/WB

    // ================= load W2 whole into overlay region ==============================
    {
        const float4* g2 = (const float4*)w2;
        #pragma unroll
        for (int l = 0; l < 8; l++) {
            int idx = tid + l * NTHREADS;
            *(float4*)&sm[W2_OFF + idx * 4] = g2[idx];
        }
    }
    __syncthreads();

    // ================= Phase 2: h2 = relu(h1 @ W2 + b2), f32x2 =======================
    {
        const int rbase = rg * 4;
        const int cbase = cg * 4;
        u64 acc2[4][2];
        #pragma unroll
        for (int i = 0; i < 4; i++) { acc2[i][0] = 0ull; acc2[i][1] = 0ull; }

        #pragma unroll 4
        for (int k = 0; k < 128; k += 4) {
            float xs[4][4];
            #pragma unroll
            for (int i = 0; i < 4; i++) {
                float4 v = *(const float4*)&sm[H1_OFF + (rbase + i) * H1LD + k];
                xs[i][0] = v.x; xs[i][1] = v.y; xs[i][2] = v.z; xs[i][3] = v.w;
            }
            #pragma unroll
            for (int q = 0; q < 4; q++) {
                ulonglong2 w = *(const ulonglong2*)&sm[W2_OFF + (k + q) * 64 + cbase];
                #pragma unroll
                for (int i = 0; i < 4; i++) {
                    u64 xq2 = pack2(xs[i][q]);
                    acc2[i][0] = ffma2(xq2, w.x, acc2[i][0]);
                    acc2[i][1] = ffma2(xq2, w.y, acc2[i][1]);
                }
            }
        }
        float4 bb = __ldg((const float4*)&b2[cbase]);
        #pragma unroll
        for (int i = 0; i < 4; i++) {
            float2 p0 = unpack2(acc2[i][0]);
            float2 p1 = unpack2(acc2[i][1]);
            float4 o;
            o.x = fmaxf(p0.x + bb.x, 0.f);
            o.y = fmaxf(p0.y + bb.y, 0.f);
            o.z = fmaxf(p1.x + bb.z, 0.f);
            o.w = fmaxf(p1.y + bb.w, 0.f);
            *(float4*)&sm[H2_OFF + (rbase + i) * H2LD + cbase] = o;
        }
    }
    __syncthreads();   // phase-2 done reading W2

    // load W3 (2048 floats) over W2 region
    {
        const float4* g3 = (const float4*)w3;
        #pragma unroll
        for (int l = 0; l < 2; l++) {
            int idx = tid + l * NTHREADS;
            *(float4*)&sm[W3_OFF + idx * 4] = g3[idx];
        }
    }
    __syncthreads();

    // ================= Phase 3: h3 = relu(h2 @ W3 + b3) (scalar, tiny) ===============
    {
        const int rg3 = tid >> 3;       // 2 rows
        const int cg3 = tid & 7;        // 4 cols
        float acc[2][4];
        #pragma unroll
        for (int i = 0; i < 2; i++)
            #pragma unroll
            for (int j = 0; j < 4; j++) acc[i][j] = 0.f;

        #pragma unroll 4
        for (int k = 0; k < 64; k += 4) {
            float xs[2][4];
            #pragma unroll
            for (int i = 0; i < 2; i++) {
                float4 v = *(const float4*)&sm[H2_OFF + (rg3 * 2 + i) * H2LD + k];
                xs[i][0] = v.x; xs[i][1] = v.y; xs[i][2] = v.z; xs[i][3] = v.w;
            }
            #pragma unroll
            for (int q = 0; q < 4; q++) {
                float4 w = *(const float4*)&sm[W3_OFF + (k + q) * 32 + cg3 * 4];
                #pragma unroll
                for (int i = 0; i < 2; i++) {
                    float xq = xs[i][q];
                    acc[i][0] = fmaf(xq, w.x, acc[i][0]);
                    acc[i][1] = fmaf(xq, w.y, acc[i][1]);
                    acc[i][2] = fmaf(xq, w.z, acc[i][2]);
                    acc[i][3] = fmaf(xq, w.w, acc[i][3]);
                }
            }
        }
        float4 bb = __ldg((const float4*)&b3[cg3 * 4]);
        #pragma unroll
        for (int i = 0; i < 2; i++) {
            float4 o;
            o.x = fmaxf(acc[i][0] + bb.x, 0.f);
            o.y = fmaxf(acc[i][1] + bb.y, 0.f);
            o.z = fmaxf(acc[i][2] + bb.z, 0.f);
            o.w = fmaxf(acc[i][3] + bb.w, 0.f);
            *(float4*)&sm[H3_OFF + (rg3 * 2 + i) * H3LD + cg3 * 4] = o;
        }
    }
    __syncthreads();

    // ================= Final combine + sigmoid ========================================
    if (tid < MROWS) {
        float dot = 0.f;
        #pragma unroll
        for (int k = 0; k < 32; k += 4) {
            float4 h = *(const float4*)&sm[H3_OFF + tid * H3LD + k];
            float4 w = *(const float4*)&sm[WO_OFF + k];
            dot = fmaf(h.x, w.x, dot);
            dot = fmaf(h.y, w.y, dot);
            dot = fmaf(h.z, w.z, dot);
            dot = fmaf(h.w, w.w, dot);
        }
        float logit = sm[LIN_OFF + tid] + __ldg(lin_b)
                    + sm[FM2_OFF + tid]
                    + dot + __ldg(bo) + __ldg(bias);
        out[r0 + tid] = 1.f / (1.f + expf(-logit));
    }
}

extern "C" void kernel_launch(void* const* d_in, const int* in_sizes, int n_in,
                              void* d_out, int out_size)
{
    (void)in_sizes; (void)n_in; (void)out_size;
    const float* x     = (const float*)d_in[0];
    const float* fm_w  = (const float*)d_in[1];
    const float* fm_b  = (const float*)d_in[2];
    const float* lin_w = (const float*)d_in[3];
    const float* lin_b = (const float*)d_in[4];
    const float* w1    = (const float*)d_in[5];
    const float* b1    = (const float*)d_in[6];
    const float* w2    = (const float*)d_in[7];
    const float* b2    = (const float*)d_in[8];
    const float* w3    = (const float*)d_in[9];
    const float* b3    = (const float*)d_in[10];
    const float* wo    = (const float*)d_in[11];
    const float* bo    = (const float*)d_in[12];
    const float* bias  = (const float*)d_in[13];

    const size_t smem_bytes = (size_t)SMEM_FLOATS * sizeof(float);
    cudaFuncSetAttribute(deepfm_fused_kernel,
                         cudaFuncAttributeMaxDynamicSharedMemorySize,
                         (int)smem_bytes);

    deepfm_fused_kernel<<<16384 / MROWS, NTHREADS, smem_bytes>>>(
        x, fm_w, fm_b, lin_w, lin_b, w1, b1, w2, b2, w3, b3, wo, bo, bias,
        (float*)d_out);
}

// round 6
// speedup vs baseline: 1.0107x; 1.0107x over previous
#include <cuda_runtime.h>
#include <math.h>

#define NTHREADS 256
#define MROWS    64

typedef unsigned long long u64;

__device__ __forceinline__ u64 ffma2(u64 a, u64 b, u64 c) {
    u64 d;
    asm("fma.rn.f32x2 %0, %1, %2, %3;" : "=l"(d) : "l"(a), "l"(b), "l"(c));
    return d;
}
__device__ __forceinline__ u64 pack2(float x) {
    unsigned xi = __float_as_uint(x);
    u64 r;
    asm("mov.b64 %0, {%1, %2};" : "=l"(r) : "r"(xi), "r"(xi));
    return r;
}
__device__ __forceinline__ float2 unpack2(u64 v) {
    unsigned lo, hi;
    asm("mov.b64 {%0, %1}, %2;" : "=r"(lo), "=r"(hi) : "l"(v));
    return make_float2(__uint_as_float(lo), __uint_as_float(hi));
}

// ---- shared memory layout (float offsets) ----
#define XB_OFF   0          // phase1 x chunk [64][36]=2304 ; FM x chunk [64][68]=4352
#define XB1LD    36
#define XBFLD    68
#define WB_OFF   4352       // phase1 w chunk [32][128]=4096 ; FM a[64][16]+b[64][16] ; scratch
#define H1_OFF   12544      // [64][132] = 8448 -> ends 20992
#define H1LD     132
#define LIN_OFF  20992      // 64
#define FM2_OFF  21056      // 64
#define SB_OFF   21120      // 16
#define LINW_OFF 21136      // 512
#define WO_OFF   21648      // 32
#define SMEM_FLOATS 21680   // 86720 bytes -> 2 CTAs/SM
// overlays after FM is done with XB/WB:
#define W2_OFF   0          // 8192
#define H2_OFF   8192       // [64][68] = 4352 -> ends exactly at 12544 (H1 start)
#define H2LD     68
#define W3_OFF   0          // 2048 (loaded after phase2 finishes reading W2)
#define H3_OFF   2048       // [64][36] = 2304
#define H3LD     36

extern __shared__ float sm[];

__global__ __launch_bounds__(NTHREADS, 2)
void deepfm_fused_kernel(
    const float* __restrict__ x,     const float* __restrict__ fm_w,
    const float* __restrict__ fm_b,  const float* __restrict__ lin_w,
    const float* __restrict__ lin_b, const float* __restrict__ w1,
    const float* __restrict__ b1,    const float* __restrict__ w2,
    const float* __restrict__ b2,    const float* __restrict__ w3,
    const float* __restrict__ b3,    const float* __restrict__ wo,
    const float* __restrict__ bo,    const float* __restrict__ bias,
    float* __restrict__ out)
{
    const int tid = threadIdx.x;
    const int r0  = blockIdx.x * MROWS;
    const float4* gx = (const float4*)(x + (size_t)r0 * 512);

    // lane-mapped tiling: within a warp, 4 row-groups x 8 col-groups (cuts smem wavefronts)
    const int rg = (tid & 3) | (((tid >> 5) & 3) << 2);   // 0..15
    const int cg = ((tid >> 2) & 7) | ((tid >> 7) << 3);  // 0..15

    // stage lin_w (512) and wo (32) once
    if (tid < 128) {
        *(float4*)&sm[LINW_OFF + tid * 4] = ((const float4*)lin_w)[tid];
    } else if (tid < 136) {
        *(float4*)&sm[WO_OFF + (tid - 128) * 4] = ((const float4*)wo)[tid - 128];
    }

    // ================= Phase 1: h1 = relu(x @ W1 + b1), f32x2 packed =================
    {
        const int rbase = rg * 4;
        const int cbase = cg * 8;
        u64 acc2[4][4];
        #pragma unroll
        for (int i = 0; i < 4; i++)
            #pragma unroll
            for (int j = 0; j < 4; j++) acc2[i][j] = 0ull;

        for (int k0 = 0; k0 < 512; k0 += 32) {
            __syncthreads();
            // stage x[:, k0:k0+32] -> XB [64][36]
            #pragma unroll
            for (int l = 0; l < 2; l++) {
                int idx = tid + l * NTHREADS;          // 512 float4s
                int row = idx >> 3, c4 = idx & 7;
                *(float4*)&sm[XB_OFF + row * XB1LD + c4 * 4] = gx[row * 128 + (k0 >> 2) + c4];
            }
            // stage w1[k0:k0+32, :] -> WB (contiguous 4096 floats)
            const float4* gw = (const float4*)(w1 + k0 * 128);
            #pragma unroll
            for (int l = 0; l < 4; l++) {
                int idx = tid + l * NTHREADS;
                *(float4*)&sm[WB_OFF + idx * 4] = gw[idx];
            }
            __syncthreads();

            #pragma unroll
            for (int kk = 0; kk < 32; kk += 4) {
                float xs[4][4];
                #pragma unroll
                for (int i = 0; i < 4; i++) {
                    float4 v = *(const float4*)&sm[XB_OFF + (rbase + i) * XB1LD + kk];
                    xs[i][0] = v.x; xs[i][1] = v.y; xs[i][2] = v.z; xs[i][3] = v.w;
                }
                #pragma unroll
                for (int q = 0; q < 4; q++) {
                    ulonglong2 wa = *(const ulonglong2*)&sm[WB_OFF + (kk + q) * 128 + cbase];
                    ulonglong2 wb = *(const ulonglong2*)&sm[WB_OFF + (kk + q) * 128 + cbase + 4];
                    #pragma unroll
                    for (int i = 0; i < 4; i++) {
                        u64 xq2 = pack2(xs[i][q]);
                        acc2[i][0] = ffma2(xq2, wa.x, acc2[i][0]);
                        acc2[i][1] = ffma2(xq2, wa.y, acc2[i][1]);
                        acc2[i][2] = ffma2(xq2, wb.x, acc2[i][2]);
                        acc2[i][3] = ffma2(xq2, wb.y, acc2[i][3]);
                    }
                }
            }
        }
        // epilogue: +b1, relu, -> h1
        float4 bb0 = __ldg((const float4*)&b1[cbase]);
        float4 bb1 = __ldg((const float4*)&b1[cbase + 4]);
        #pragma unroll
        for (int i = 0; i < 4; i++) {
            float2 p0 = unpack2(acc2[i][0]);
            float2 p1 = unpack2(acc2[i][1]);
            float2 p2 = unpack2(acc2[i][2]);
            float2 p3 = unpack2(acc2[i][3]);
            float4 o0, o1;
            o0.x = fmaxf(p0.x + bb0.x, 0.f);
            o0.y = fmaxf(p0.y + bb0.y, 0.f);
            o0.z = fmaxf(p1.x + bb0.z, 0.f);
            o0.w = fmaxf(p1.y + bb0.w, 0.f);
            o1.x = fmaxf(p2.x + bb1.x, 0.f);
            o1.y = fmaxf(p2.y + bb1.y, 0.f);
            o1.z = fmaxf(p3.x + bb1.z, 0.f);
            o1.w = fmaxf(p3.y + bb1.w, 0.f);
            *(float4*)&sm[H1_OFF + (rbase + i) * H1LD + cbase]     = o0;
            *(float4*)&sm[H1_OFF + (rbase + i) * H1LD + cbase + 4] = o1;
        }
    }
    __syncthreads();   // phase-1 done reading WB

    // ================= Sb precompute: Sb[d] = sum_k fm_b[k][d]  (row-independent) =====
    {
        int d = tid & 15, seg = tid >> 4;
        float p = 0.f;
        #pragma unroll 8
        for (int j = 0; j < 32; j++) p += __ldg(&fm_b[(seg * 32 + j) * 16 + d]);
        sm[WB_OFF + seg * 16 + d] = p;   // WB as scratch
    }
    __syncthreads();
    if (tid < 16) {
        float s = 0.f;
        #pragma unroll
        for (int seg = 0; seg < 16; seg++) s += sm[WB_OFF + seg * 16 + tid];
        sm[SB_OFF + tid] = s;
    }

    // ================= FM phase (f32x2), streams x + fm_w/fm_b chunks ================
    {
        const int row = tid >> 2;      // 64 rows
        const int dg  = tid & 3;       // 2 d-pairs per thread
        u64 ssum2[2] = {0ull, 0ull};
        u64 ssq2[2]  = {0ull, 0ull};
        float s_lin = 0.f;

        for (int k0 = 0; k0 < 512; k0 += 64) {
            __syncthreads();   // also covers Sb scratch reads on first iter
            #pragma unroll
            for (int l = 0; l < 4; l++) {
                int idx = tid + l * NTHREADS;       // 1024 float4s
                int r = idx >> 4, c4 = idx & 15;
                *(float4*)&sm[XB_OFF + r * XBFLD + c4 * 4] = gx[r * 128 + (k0 >> 2) + c4];
            }
            *(float4*)&sm[WB_OFF + tid * 4]        = ((const float4*)(fm_w + k0 * 16))[tid];
            *(float4*)&sm[WB_OFF + 1024 + tid * 4] = ((const float4*)(fm_b + k0 * 16))[tid];
            __syncthreads();

            #pragma unroll 4
            for (int kk = 0; kk < 64; kk++) {
                float xv = sm[XB_OFF + row * XBFLD + kk];
                u64 x2 = pack2(xv);
                ulonglong2 a = *(const ulonglong2*)&sm[WB_OFF + kk * 16 + dg * 4];
                ulonglong2 b = *(const ulonglong2*)&sm[WB_OFF + 1024 + kk * 16 + dg * 4];
                ssum2[0] = ffma2(x2, a.x, ssum2[0]);
                ssum2[1] = ffma2(x2, a.y, ssum2[1]);
                u64 t0 = ffma2(x2, a.x, b.x);
                u64 t1 = ffma2(x2, a.y, b.y);
                ssq2[0] = ffma2(t0, t0, ssq2[0]);
                ssq2[1] = ffma2(t1, t1, ssq2[1]);
                if (dg == 0) s_lin = fmaf(xv, sm[LINW_OFF + k0 + kk], s_lin);
            }
        }
        float2 s0 = unpack2(ssum2[0]), s1 = unpack2(ssum2[1]);
        float2 q0 = unpack2(ssq2[0]),  q1 = unpack2(ssq2[1]);
        const int db = dg * 4;
        float v = 0.f, se;
        se = s0.x + sm[SB_OFF + db + 0]; v += se * se - q0.x;
        se = s0.y + sm[SB_OFF + db + 1]; v += se * se - q0.y;
        se = s1.x + sm[SB_OFF + db + 2]; v += se * se - q1.x;
        se = s1.y + sm[SB_OFF + db + 3]; v += se * se - q1.y;
        v += __shfl_xor_sync(0xffffffffu, v, 1);
        v += __shfl_xor_sync(0xffffffffu, v, 2);
        if (dg == 0) {
            sm[FM2_OFF + row] = 0.5f * v;
            sm[LIN_OFF + row] = s_lin;
        }
    }
    __syncthreads();   // FM done with XB/WB

    // ================= load W2 whole into overlay region ==============================
    {
        const float4* g2 = (const float4*)w2;
        #pragma unroll
        for (int l = 0; l < 8; l++) {
            int idx = tid + l * NTHREADS;
            *(float4*)&sm[W2_OFF + idx * 4] = g2[idx];
        }
    }
    __syncthreads();

    // ================= Phase 2: h2 = relu(h1 @ W2 + b2), f32x2 =======================
    {
        const int rbase = rg * 4;
        const int cbase = cg * 4;
        u64 acc2[4][2];
        #pragma unroll
        for (int i = 0; i < 4; i++) { acc2[i][0] = 0ull; acc2[i][1] = 0ull; }

        #pragma unroll 4
        for (int k = 0; k < 128; k += 4) {
            float xs[4][4];
            #pragma unroll
            for (int i = 0; i < 4; i++) {
                float4 v = *(const float4*)&sm[H1_OFF + (rbase + i) * H1LD + k];
                xs[i][0] = v.x; xs[i][1] = v.y; xs[i][2] = v.z; xs[i][3] = v.w;
            }
            #pragma unroll
            for (int q = 0; q < 4; q++) {
                ulonglong2 w = *(const ulonglong2*)&sm[W2_OFF + (k + q) * 64 + cbase];
                #pragma unroll
                for (int i = 0; i < 4; i++) {
                    u64 xq2 = pack2(xs[i][q]);
                    acc2[i][0] = ffma2(xq2, w.x, acc2[i][0]);
                    acc2[i][1] = ffma2(xq2, w.y, acc2[i][1]);
                }
            }
        }
        float4 bb = __ldg((const float4*)&b2[cbase]);
        #pragma unroll
        for (int i = 0; i < 4; i++) {
            float2 p0 = unpack2(acc2[i][0]);
            float2 p1 = unpack2(acc2[i][1]);
            float4 o;
            o.x = fmaxf(p0.x + bb.x, 0.f);
            o.y = fmaxf(p0.y + bb.y, 0.f);
            o.z = fmaxf(p1.x + bb.z, 0.f);
            o.w = fmaxf(p1.y + bb.w, 0.f);
            *(float4*)&sm[H2_OFF + (rbase + i) * H2LD + cbase] = o;
        }
    }
    __syncthreads();   // phase-2 done reading W2

    // load W3 (2048 floats) over W2 region
    {
        const float4* g3 = (const float4*)w3;
        #pragma unroll
        for (int l = 0; l < 2; l++) {
            int idx = tid + l * NTHREADS;
            *(float4*)&sm[W3_OFF + idx * 4] = g3[idx];
        }
    }
    __syncthreads();

    // ================= Phase 3: h3 = relu(h2 @ W3 + b3) (scalar, tiny) ===============
    {
        const int rg3 = tid >> 3;       // 2 rows
        const int cg3 = tid & 7;        // 4 cols
        float acc[2][4];
        #pragma unroll
        for (int i = 0; i < 2; i++)
            #pragma unroll
            for (int j = 0; j < 4; j++) acc[i][j] = 0.f;

        #pragma unroll 4
        for (int k = 0; k < 64; k += 4) {
            float xs[2][4];
            #pragma unroll
            for (int i = 0; i < 2; i++) {
                float4 v = *(const float4*)&sm[H2_OFF + (rg3 * 2 + i) * H2LD + k];
                xs[i][0] = v.x; xs[i][1] = v.y; xs[i][2] = v.z; xs[i][3] = v.w;
            }
            #pragma unroll
            for (int q = 0; q < 4; q++) {
                float4 w = *(const float4*)&sm[W3_OFF + (k + q) * 32 + cg3 * 4];
                #pragma unroll
                for (int i = 0; i < 2; i++) {
                    float xq = xs[i][q];
                    acc[i][0] = fmaf(xq, w.x, acc[i][0]);
                    acc[i][1] = fmaf(xq, w.y, acc[i][1]);
                    acc[i][2] = fmaf(xq, w.z, acc[i][2]);
                    acc[i][3] = fmaf(xq, w.w, acc[i][3]);
                }
            }
        }
        float4 bb = __ldg((const float4*)&b3[cg3 * 4]);
        #pragma unroll
        for (int i = 0; i < 2; i++) {
            float4 o;
            o.x = fmaxf(acc[i][0] + bb.x, 0.f);
            o.y = fmaxf(acc[i][1] + bb.y, 0.f);
            o.z = fmaxf(acc[i][2] + bb.z, 0.f);
            o.w = fmaxf(acc[i][3] + bb.w, 0.f);
            *(float4*)&sm[H3_OFF + (rg3 * 2 + i) * H3LD + cg3 * 4] = o;
        }
    }
    __syncthreads();

    // ================= Final combine + sigmoid ========================================
    if (tid < MROWS) {
        float dot = 0.f;
        #pragma unroll
        for (int k = 0; k < 32; k += 4) {
            float4 h = *(const float4*)&sm[H3_OFF + tid * H3LD + k];
            float4 w = *(const float4*)&sm[WO_OFF + k];
            dot = fmaf(h.x, w.x, dot);
            dot = fmaf(h.y, w.y, dot);
            dot = fmaf(h.z, w.z, dot);
            dot = fmaf(h.w, w.w, dot);
        }
        float logit = sm[LIN_OFF + tid] + __ldg(lin_b)
                    + sm[FM2_OFF + tid]
                    + dot + __ldg(bo) + __ldg(bias);
        out[r0 + tid] = 1.f / (1.f + expf(-logit));
    }
}

extern "C" void kernel_launch(void* const* d_in, const int* in_sizes, int n_in,
                              void* d_out, int out_size)
{
    (void)in_sizes; (void)n_in; (void)out_size;
    const float* x     = (const float*)d_in[0];
    const float* fm_w  = (const float*)d_in[1];
    const float* fm_b  = (const float*)d_in[2];
    const float* lin_w = (const float*)d_in[3];
    const float* lin_b = (const float*)d_in[4];
    const float* w1    = (const float*)d_in[5];
    const float* b1    = (const float*)d_in[6];
    const float* w2    = (const float*)d_in[7];
    const float* b2    = (const float*)d_in[8];
    const float* w3    = (const float*)d_in[9];
    const float* b3    = (const float*)d_in[10];
    const float* wo    = (const float*)d_in[11];
    const float* bo    = (const float*)d_in[12];
    const float* bias  = (const float*)d_in[13];

    const size_t smem_bytes = (size_t)SMEM_FLOATS * sizeof(float);
    cudaFuncSetAttribute(deepfm_fused_kernel,
                         cudaFuncAttributeMaxDynamicSharedMemorySize,
                         (int)smem_bytes);

    deepfm_fused_kernel<<<16384 / MROWS, NTHREADS, smem_bytes>>>(
        x, fm_w, fm_b, lin_w, lin_b, w1, b1, w2, b2, w3, b3, wo, bo, bias,
        (float*)d_out);
}